// round 1
// baseline (speedup 1.0000x reference)
#include <cuda_runtime.h>
#include <cuda_bf16.h>
#include <cstdint>

// Problem constants
#define BB 4
#define NN_SEQ 1024
#define CC 768
#define HH 12
#define HD 64
#define NN2 (NN_SEQ * NN_SEQ)          // 1048576
#define SCALE 0.125f                    // 64^-0.5

// Scratch (device globals: allocation-guard safe)
__device__ float g_q[BB * HH * NN_SEQ * HD];     // (b,h,n,d), pre-scaled
__device__ float g_k[BB * HH * NN_SEQ * HD];
__device__ float g_v[BB * HH * NN_SEQ * HD];
__device__ float g_att[BB * HH * NN_SEQ * NN_SEQ]; // (b,h,q,k) -> then post-mix probs
__device__ float g_x[BB * NN_SEQ * CC];          // (b,q, g*64+d)

// ---------------------------------------------------------------------------
// tf32 helpers
// ---------------------------------------------------------------------------
__device__ __forceinline__ unsigned f2tf32(float x) {
    unsigned u;
    asm("cvt.rna.tf32.f32 %0, %1;" : "=r"(u) : "f"(x));
    return u;
}

__device__ __forceinline__ void mma_tf32(float* c, const unsigned* a, const unsigned* b) {
    asm volatile(
        "mma.sync.aligned.m16n8k8.row.col.f32.tf32.tf32.f32 "
        "{%0,%1,%2,%3}, {%4,%5,%6,%7}, {%8,%9}, {%0,%1,%2,%3};\n"
        : "+f"(c[0]), "+f"(c[1]), "+f"(c[2]), "+f"(c[3])
        : "r"(a[0]), "r"(a[1]), "r"(a[2]), "r"(a[3]), "r"(b[0]), "r"(b[1]));
}

// ---------------------------------------------------------------------------
// Kernel 1: QKV GEMM.  X(4096x768) @ W(768x2304) -> split into g_q/g_k/g_v.
// CTA tile 128x64, BK=32. 256 threads, 8 warps in 4x2 grid, warp tile 32x32.
// ---------------------------------------------------------------------------
__global__ __launch_bounds__(256) void qkv_kernel(const float* __restrict__ X,
                                                  const float* __restrict__ W) {
    __shared__ unsigned As[128][36];  // [m][k]  stride 36 -> conflict-free frags
    __shared__ unsigned Bs[32][72];   // [k][n]  stride 72 -> conflict-free frags

    const int tid = threadIdx.x, lane = tid & 31, warp = tid >> 5;
    const int wm = warp >> 1, wn = warp & 1;
    const int m0 = blockIdx.y * 128, n0 = blockIdx.x * 64;

    float acc[2][4][4];
#pragma unroll
    for (int i = 0; i < 2; i++)
#pragma unroll
        for (int j = 0; j < 4; j++)
#pragma unroll
            for (int l = 0; l < 4; l++) acc[i][j][l] = 0.f;

    for (int kt = 0; kt < 768; kt += 32) {
        // load A tile 128x32 (4 float4 / thread)
#pragma unroll
        for (int i = 0; i < 4; i++) {
            int f = tid + i * 256;
            int r = f >> 3, c4 = (f & 7) * 4;
            float4 v = *(const float4*)(X + (size_t)(m0 + r) * 768 + kt + c4);
            As[r][c4 + 0] = f2tf32(v.x);
            As[r][c4 + 1] = f2tf32(v.y);
            As[r][c4 + 2] = f2tf32(v.z);
            As[r][c4 + 3] = f2tf32(v.w);
        }
        // load B tile 32x64 (2 float4 / thread)
#pragma unroll
        for (int i = 0; i < 2; i++) {
            int f = tid + i * 256;
            int r = f >> 4, c4 = (f & 15) * 4;
            float4 v = *(const float4*)(W + (size_t)(kt + r) * 2304 + n0 + c4);
            Bs[r][c4 + 0] = f2tf32(v.x);
            Bs[r][c4 + 1] = f2tf32(v.y);
            Bs[r][c4 + 2] = f2tf32(v.z);
            Bs[r][c4 + 3] = f2tf32(v.w);
        }
        __syncthreads();
#pragma unroll
        for (int ks = 0; ks < 4; ks++) {
            unsigned a[2][4], b[4][2];
#pragma unroll
            for (int mi = 0; mi < 2; mi++) {
                int r = wm * 32 + mi * 16 + (lane >> 2);
                int c = ks * 8 + (lane & 3);
                a[mi][0] = As[r][c];
                a[mi][1] = As[r + 8][c];
                a[mi][2] = As[r][c + 4];
                a[mi][3] = As[r + 8][c + 4];
            }
#pragma unroll
            for (int ni = 0; ni < 4; ni++) {
                int c = wn * 32 + ni * 8 + (lane >> 2);
                int rk = ks * 8 + (lane & 3);
                b[ni][0] = Bs[rk][c];
                b[ni][1] = Bs[rk + 4][c];
            }
#pragma unroll
            for (int mi = 0; mi < 2; mi++)
#pragma unroll
                for (int ni = 0; ni < 4; ni++) mma_tf32(acc[mi][ni], a[mi], b[ni]);
        }
        __syncthreads();
    }

    // Epilogue: column block n0..n0+63 lies entirely inside one (t,h) slab.
    const int t = n0 / 768;                 // 0=q 1=k 2=v
    const int hh = (n0 % 768) >> 6;         // head
    float* dst = (t == 0) ? g_q : (t == 1) ? g_k : g_v;
    const float sc = (t == 0) ? SCALE : 1.0f;

#pragma unroll
    for (int mi = 0; mi < 2; mi++)
#pragma unroll
        for (int ni = 0; ni < 4; ni++) {
            int row = m0 + wm * 32 + mi * 16 + (lane >> 2);
            int col = n0 + wn * 32 + ni * 8 + 2 * (lane & 3);
            int d = col & 63;
            int bb = row >> 10, ns = row & 1023;
            size_t base0 = ((size_t)(bb * HH + hh) * NN_SEQ + ns) * HD;
            size_t base1 = ((size_t)(bb * HH + hh) * NN_SEQ + (ns + 8)) * HD;
            dst[base0 + d]     = acc[mi][ni][0] * sc;
            dst[base0 + d + 1] = acc[mi][ni][1] * sc;
            dst[base1 + d]     = acc[mi][ni][2] * sc;
            dst[base1 + d + 1] = acc[mi][ni][3] * sc;
        }
}

// ---------------------------------------------------------------------------
// Kernel 2: S = Q @ K^T per (b,h).  M=N=1024, K=64. CTA tile 128(q) x 64(k).
// ---------------------------------------------------------------------------
__global__ __launch_bounds__(256) void qk_kernel() {
    __shared__ unsigned As[128][36];  // [q][d]
    __shared__ unsigned Bs[64][36];   // [kidx][d]

    const int tid = threadIdx.x, lane = tid & 31, warp = tid >> 5;
    const int wm = warp >> 1, wn = warp & 1;
    const int z = blockIdx.z;
    const int q0 = blockIdx.y * 128, n0 = blockIdx.x * 64;
    const float* A = g_q + (size_t)z * NN_SEQ * HD;
    const float* Bm = g_k + (size_t)z * NN_SEQ * HD;

    float acc[2][4][4];
#pragma unroll
    for (int i = 0; i < 2; i++)
#pragma unroll
        for (int j = 0; j < 4; j++)
#pragma unroll
            for (int l = 0; l < 4; l++) acc[i][j][l] = 0.f;

    for (int dt = 0; dt < 64; dt += 32) {
#pragma unroll
        for (int i = 0; i < 4; i++) {  // A: 128x32
            int f = tid + i * 256;
            int r = f >> 3, c4 = (f & 7) * 4;
            float4 v = *(const float4*)(A + (size_t)(q0 + r) * 64 + dt + c4);
            As[r][c4 + 0] = f2tf32(v.x);
            As[r][c4 + 1] = f2tf32(v.y);
            As[r][c4 + 2] = f2tf32(v.z);
            As[r][c4 + 3] = f2tf32(v.w);
        }
#pragma unroll
        for (int i = 0; i < 2; i++) {  // B: 64x32 ([kidx][d])
            int f = tid + i * 256;
            int r = f >> 3, c4 = (f & 7) * 4;
            float4 v = *(const float4*)(Bm + (size_t)(n0 + r) * 64 + dt + c4);
            Bs[r][c4 + 0] = f2tf32(v.x);
            Bs[r][c4 + 1] = f2tf32(v.y);
            Bs[r][c4 + 2] = f2tf32(v.z);
            Bs[r][c4 + 3] = f2tf32(v.w);
        }
        __syncthreads();
#pragma unroll
        for (int ks = 0; ks < 4; ks++) {
            unsigned a[2][4], b[4][2];
#pragma unroll
            for (int mi = 0; mi < 2; mi++) {
                int r = wm * 32 + mi * 16 + (lane >> 2);
                int c = ks * 8 + (lane & 3);
                a[mi][0] = As[r][c];
                a[mi][1] = As[r + 8][c];
                a[mi][2] = As[r][c + 4];
                a[mi][3] = As[r + 8][c + 4];
            }
#pragma unroll
            for (int ni = 0; ni < 4; ni++) {
                int n = wn * 32 + ni * 8 + (lane >> 2);
                int rk = ks * 8 + (lane & 3);
                b[ni][0] = Bs[n][rk];
                b[ni][1] = Bs[n][rk + 4];
            }
#pragma unroll
            for (int mi = 0; mi < 2; mi++)
#pragma unroll
                for (int ni = 0; ni < 4; ni++) mma_tf32(acc[mi][ni], a[mi], b[ni]);
        }
        __syncthreads();
    }

    float* O = g_att + (size_t)z * NN2;
#pragma unroll
    for (int mi = 0; mi < 2; mi++)
#pragma unroll
        for (int ni = 0; ni < 4; ni++) {
            int row = q0 + wm * 32 + mi * 16 + (lane >> 2);
            int col = n0 + wn * 32 + ni * 8 + 2 * (lane & 3);
            O[(size_t)row * NN_SEQ + col]       = acc[mi][ni][0];
            O[(size_t)row * NN_SEQ + col + 1]   = acc[mi][ni][1];
            O[(size_t)(row + 8) * NN_SEQ + col]     = acc[mi][ni][2];
            O[(size_t)(row + 8) * NN_SEQ + col + 1] = acc[mi][ni][3];
        }
}

// ---------------------------------------------------------------------------
// Kernel 3: per (b,q): pre-mix (12x12) -> softmax over k -> post-mix (12x12).
// CTA = one (b,q). Holds all 12 head rows (12x1024 f32 = 48KB) in dyn smem.
// ---------------------------------------------------------------------------
__global__ __launch_bounds__(256) void mix_kernel(const float* __restrict__ wl,
                                                  const float* __restrict__ bl,
                                                  const float* __restrict__ ww,
                                                  const float* __restrict__ bw) {
    extern __shared__ float sm[];
    float* S   = sm;             // 12*1024
    float* red = S + 12 * 1024;  // 96
    float* sM  = red + 96;       // 12
    float* sIl = sM + 12;        // 12
    float* sWl = sIl + 12;       // 144
    float* sWw = sWl + 144;      // 144
    float* sBl = sWw + 144;      // 12
    float* sBw = sBl + 12;       // 12

    const int tid = threadIdx.x, lane = tid & 31, warp = tid >> 5;
    const int bq = blockIdx.x;
    const int b = bq >> 10, q = bq & 1023;
    const size_t base = (size_t)(b * HH) * NN2 + (size_t)q * NN_SEQ;

    if (tid < 144) { sWl[tid] = wl[tid]; sWw[tid] = ww[tid]; }
    if (tid < 12)  { sBl[tid] = bl[tid]; sBw[tid] = bw[tid]; }

#pragma unroll
    for (int h = 0; h < 12; h++) {
        float4 v = *(const float4*)(g_att + base + (size_t)h * NN2 + tid * 4);
        *(float4*)&S[h * 1024 + tid * 4] = v;
    }
    __syncthreads();

    // pre-mix + running max
    float pmax[12];
#pragma unroll
    for (int g = 0; g < 12; g++) pmax[g] = -1e30f;

#pragma unroll
    for (int j = 0; j < 4; j++) {
        int k = tid + j * 256;
        float s[12];
#pragma unroll
        for (int h = 0; h < 12; h++) s[h] = S[h * 1024 + k];
#pragma unroll
        for (int g = 0; g < 12; g++) {
            float v = sBl[g];
#pragma unroll
            for (int h = 0; h < 12; h++) v += s[h] * sWl[h * 12 + g];
            S[g * 1024 + k] = v;
            pmax[g] = fmaxf(pmax[g], v);
        }
    }

    // reduce max
#pragma unroll
    for (int g = 0; g < 12; g++) {
        float m = pmax[g];
#pragma unroll
        for (int off = 16; off; off >>= 1) m = fmaxf(m, __shfl_xor_sync(0xffffffffu, m, off));
        if (lane == 0) red[warp * 12 + g] = m;
    }
    __syncthreads();
    if (tid < 12) {
        float m = red[tid];
#pragma unroll
        for (int w = 1; w < 8; w++) m = fmaxf(m, red[w * 12 + tid]);
        sM[tid] = m;
    }
    __syncthreads();

    // exp + partial sums
    float psum[12];
#pragma unroll
    for (int g = 0; g < 12; g++) psum[g] = 0.f;
#pragma unroll
    for (int j = 0; j < 4; j++) {
        int k = tid + j * 256;
#pragma unroll
        for (int g = 0; g < 12; g++) {
            float p = __expf(S[g * 1024 + k] - sM[g]);
            S[g * 1024 + k] = p;
            psum[g] += p;
        }
    }
#pragma unroll
    for (int g = 0; g < 12; g++) {
        float s = psum[g];
#pragma unroll
        for (int off = 16; off; off >>= 1) s += __shfl_xor_sync(0xffffffffu, s, off);
        if (lane == 0) red[warp * 12 + g] = s;
    }
    __syncthreads();
    if (tid < 12) {
        float s = red[tid];
#pragma unroll
        for (int w = 1; w < 8; w++) s += red[w * 12 + tid];
        sIl[tid] = 1.0f / s;
    }
    __syncthreads();

    // post-mix -> write normalized mixed probs back to g_att
#pragma unroll
    for (int j = 0; j < 4; j++) {
        int k = tid + j * 256;
        float p[12];
#pragma unroll
        for (int h = 0; h < 12; h++) p[h] = S[h * 1024 + k] * sIl[h];
#pragma unroll
        for (int g = 0; g < 12; g++) {
            float v = sBw[g];
#pragma unroll
            for (int h = 0; h < 12; h++) v += p[h] * sWw[h * 12 + g];
            g_att[base + (size_t)g * NN2 + k] = v;
        }
    }
}

// ---------------------------------------------------------------------------
// Kernel 4: X = P @ V per (b,g). M=1024, N=64, K=1024. CTA tile 128x64.
// ---------------------------------------------------------------------------
__global__ __launch_bounds__(256) void av_kernel() {
    __shared__ unsigned As[128][36];  // [q][kidx]
    __shared__ unsigned Bs[32][72];   // [kidx][d]

    const int tid = threadIdx.x, lane = tid & 31, warp = tid >> 5;
    const int wm = warp >> 1, wn = warp & 1;
    const int z = blockIdx.y;
    const int q0 = blockIdx.x * 128;
    const float* A = g_att + (size_t)z * NN2;
    const float* V = g_v + (size_t)z * NN_SEQ * HD;

    float acc[2][4][4];
#pragma unroll
    for (int i = 0; i < 2; i++)
#pragma unroll
        for (int j = 0; j < 4; j++)
#pragma unroll
            for (int l = 0; l < 4; l++) acc[i][j][l] = 0.f;

    for (int k0 = 0; k0 < 1024; k0 += 32) {
#pragma unroll
        for (int i = 0; i < 4; i++) {  // A: 128x32
            int f = tid + i * 256;
            int r = f >> 3, c4 = (f & 7) * 4;
            float4 v = *(const float4*)(A + (size_t)(q0 + r) * 1024 + k0 + c4);
            As[r][c4 + 0] = f2tf32(v.x);
            As[r][c4 + 1] = f2tf32(v.y);
            As[r][c4 + 2] = f2tf32(v.z);
            As[r][c4 + 3] = f2tf32(v.w);
        }
#pragma unroll
        for (int i = 0; i < 2; i++) {  // B: 32x64
            int f = tid + i * 256;
            int r = f >> 4, c4 = (f & 15) * 4;
            float4 v = *(const float4*)(V + (size_t)(k0 + r) * 64 + c4);
            Bs[r][c4 + 0] = f2tf32(v.x);
            Bs[r][c4 + 1] = f2tf32(v.y);
            Bs[r][c4 + 2] = f2tf32(v.z);
            Bs[r][c4 + 3] = f2tf32(v.w);
        }
        __syncthreads();
#pragma unroll
        for (int ks = 0; ks < 4; ks++) {
            unsigned a[2][4], b[4][2];
#pragma unroll
            for (int mi = 0; mi < 2; mi++) {
                int r = wm * 32 + mi * 16 + (lane >> 2);
                int c = ks * 8 + (lane & 3);
                a[mi][0] = As[r][c];
                a[mi][1] = As[r + 8][c];
                a[mi][2] = As[r][c + 4];
                a[mi][3] = As[r + 8][c + 4];
            }
#pragma unroll
            for (int ni = 0; ni < 4; ni++) {
                int c = wn * 32 + ni * 8 + (lane >> 2);
                int rk = ks * 8 + (lane & 3);
                b[ni][0] = Bs[rk][c];
                b[ni][1] = Bs[rk + 4][c];
            }
#pragma unroll
            for (int mi = 0; mi < 2; mi++)
#pragma unroll
                for (int ni = 0; ni < 4; ni++) mma_tf32(acc[mi][ni], a[mi], b[ni]);
        }
        __syncthreads();
    }

    const int bb = z / HH, g = z % HH;
#pragma unroll
    for (int mi = 0; mi < 2; mi++)
#pragma unroll
        for (int ni = 0; ni < 4; ni++) {
            int row = q0 + wm * 32 + mi * 16 + (lane >> 2);
            int col = wn * 32 + ni * 8 + 2 * (lane & 3);  // d index 0..63
            size_t base0 = ((size_t)(bb * NN_SEQ + row) * CC) + g * HD + col;
            size_t base1 = ((size_t)(bb * NN_SEQ + row + 8) * CC) + g * HD + col;
            g_x[base0]     = acc[mi][ni][0];
            g_x[base0 + 1] = acc[mi][ni][1];
            g_x[base1]     = acc[mi][ni][2];
            g_x[base1 + 1] = acc[mi][ni][3];
        }
}

// ---------------------------------------------------------------------------
// Kernel 5: out = X @ Wp + bp.  M=4096, K=768, N=768.
// ---------------------------------------------------------------------------
__global__ __launch_bounds__(256) void proj_kernel(const float* __restrict__ Wp,
                                                   const float* __restrict__ bp,
                                                   float* __restrict__ out) {
    __shared__ unsigned As[128][36];
    __shared__ unsigned Bs[32][72];

    const int tid = threadIdx.x, lane = tid & 31, warp = tid >> 5;
    const int wm = warp >> 1, wn = warp & 1;
    const int m0 = blockIdx.y * 128, n0 = blockIdx.x * 64;

    float acc[2][4][4];
#pragma unroll
    for (int i = 0; i < 2; i++)
#pragma unroll
        for (int j = 0; j < 4; j++)
#pragma unroll
            for (int l = 0; l < 4; l++) acc[i][j][l] = 0.f;

    for (int kt = 0; kt < 768; kt += 32) {
#pragma unroll
        for (int i = 0; i < 4; i++) {
            int f = tid + i * 256;
            int r = f >> 3, c4 = (f & 7) * 4;
            float4 v = *(const float4*)(g_x + (size_t)(m0 + r) * 768 + kt + c4);
            As[r][c4 + 0] = f2tf32(v.x);
            As[r][c4 + 1] = f2tf32(v.y);
            As[r][c4 + 2] = f2tf32(v.z);
            As[r][c4 + 3] = f2tf32(v.w);
        }
#pragma unroll
        for (int i = 0; i < 2; i++) {
            int f = tid + i * 256;
            int r = f >> 4, c4 = (f & 15) * 4;
            float4 v = *(const float4*)(Wp + (size_t)(kt + r) * 768 + n0 + c4);
            Bs[r][c4 + 0] = f2tf32(v.x);
            Bs[r][c4 + 1] = f2tf32(v.y);
            Bs[r][c4 + 2] = f2tf32(v.z);
            Bs[r][c4 + 3] = f2tf32(v.w);
        }
        __syncthreads();
#pragma unroll
        for (int ks = 0; ks < 4; ks++) {
            unsigned a[2][4], b[4][2];
#pragma unroll
            for (int mi = 0; mi < 2; mi++) {
                int r = wm * 32 + mi * 16 + (lane >> 2);
                int c = ks * 8 + (lane & 3);
                a[mi][0] = As[r][c];
                a[mi][1] = As[r + 8][c];
                a[mi][2] = As[r][c + 4];
                a[mi][3] = As[r + 8][c + 4];
            }
#pragma unroll
            for (int ni = 0; ni < 4; ni++) {
                int c = wn * 32 + ni * 8 + (lane >> 2);
                int rk = ks * 8 + (lane & 3);
                b[ni][0] = Bs[rk][c];
                b[ni][1] = Bs[rk + 4][c];
            }
#pragma unroll
            for (int mi = 0; mi < 2; mi++)
#pragma unroll
                for (int ni = 0; ni < 4; ni++) mma_tf32(acc[mi][ni], a[mi], b[ni]);
        }
        __syncthreads();
    }

#pragma unroll
    for (int mi = 0; mi < 2; mi++)
#pragma unroll
        for (int ni = 0; ni < 4; ni++) {
            int row = m0 + wm * 32 + mi * 16 + (lane >> 2);
            int col = n0 + wn * 32 + ni * 8 + 2 * (lane & 3);
            float b0 = __ldg(&bp[col]), b1 = __ldg(&bp[col + 1]);
            out[(size_t)row * 768 + col]       = acc[mi][ni][0] + b0;
            out[(size_t)row * 768 + col + 1]   = acc[mi][ni][1] + b1;
            out[(size_t)(row + 8) * 768 + col]     = acc[mi][ni][2] + b0;
            out[(size_t)(row + 8) * 768 + col + 1] = acc[mi][ni][3] + b1;
        }
}

// ---------------------------------------------------------------------------
extern "C" void kernel_launch(void* const* d_in, const int* in_sizes, int n_in,
                              void* d_out, int out_size) {
    const float* X    = (const float*)d_in[0];
    const float* Wqkv = (const float*)d_in[1];
    const float* Wl   = (const float*)d_in[2];
    const float* Bl   = (const float*)d_in[3];
    const float* Ww   = (const float*)d_in[4];
    const float* Bw   = (const float*)d_in[5];
    const float* Wp   = (const float*)d_in[6];
    const float* Bp   = (const float*)d_in[7];
    float* out = (float*)d_out;

    const int mix_smem = (12 * 1024 + 96 + 12 + 12 + 144 + 144 + 12 + 12) * 4;  // 50880 B
    cudaFuncSetAttribute(mix_kernel, cudaFuncAttributeMaxDynamicSharedMemorySize, mix_smem);

    qkv_kernel<<<dim3(36, 32), 256>>>(X, Wqkv);
    qk_kernel<<<dim3(16, 8, 48), 256>>>();
    mix_kernel<<<4096, 256, mix_smem>>>(Wl, Bl, Ww, Bw);
    av_kernel<<<dim3(8, 48), 256>>>();
    proj_kernel<<<dim3(12, 32), 256>>>(Wp, Bp, out);
}